// round 7
// baseline (speedup 1.0000x reference)
#include <cuda_runtime.h>
#include <cuda_bf16.h>
#include <math.h>

// ---------------------------------------------------------------------------
// FARGAN: 100 frames x 4 subframes recurrent vocoder, B=64.
// Phase A: frame conv hoisted out of the sequential loop (3 fp32 GEMMs).
// Phase P: weight repack into coalesced [K/4][Nout][4] layout.
// Phase B: persistent recurrent kernel: 64 CTAs x 512 threads, one chain per
//          CTA. Register prefetch of gi weights across barriers, merged
//          small stages on warps 14-15 (named barrier), gh matvecs for the
//          next step computed during the latency-bound tail.
// ---------------------------------------------------------------------------

#define FRN 100

// Scratch (device globals: allocation-free rule)
__device__ float g_X [6400 * 256];
__device__ float g_H1[6400 * 256];
__device__ float g_H2[6400 * 256];
__device__ float g_C [6400 * 512];
__device__ int   g_P [6400];
__device__ float g_Wp[217344];   // packed recurrent weights

// Packed weight offsets (floats)
#define OFF_FW    0        // Wfw   64 x 388
#define OFF_FWG   24832    // Wfwg  64 x 64
#define OFF_IH1   28928    // Wih1 192 x 128
#define OFF_HH1   53504    // Whh1 192 x 64
#define OFF_IH2   65792
#define OFF_HH2   90368
#define OFF_IH3   102656
#define OFF_HH3   127232
#define OFF_G1    139520   // Wg 64 x 64
#define OFF_G2    143616
#define OFF_G3    147712
#define OFF_SD    151808   // Wsd 128 x 320
#define OFF_SG    192768   // Wsg 128 x 128
#define OFF_OUT   209152   // Wout 64 x 128

// ---------------------------------------------------------------------------
__global__ void pack_kernel(const float* __restrict__ feats,
                            const float* __restrict__ gf)
{
    int m = blockIdx.x;              // b*100 + t
    int b = m / FRN, t = m % FRN;
    int c = threadIdx.x;             // 0..255
    float v;
    if (c < 192) v = feats[b * 193 * FRN + c * FRN + t];
    else         v = gf[b * 64 + (c - 192)];
    g_X[m * 256 + c] = v;
    if (c == 0)
        g_P[m] = (int)rintf(feats[b * 193 * FRN + 192 * FRN + t]);
}

__global__ void pack_w_kernel(const float* __restrict__ src,
                              float* __restrict__ dst, int Nout, int K)
{
    int i = blockIdx.x * blockDim.x + threadIdx.x;
    if (i >= Nout * K) return;
    int r = i / K, k = i % K;
    int k4 = k >> 2, c = k & 3;
    dst[(k4 * Nout + r) * 4 + c] = src[i];
}

// ---------------------------------------------------------------------------
// Tiled NT GEMM with fused tanh
// ---------------------------------------------------------------------------
#define GBM 64
#define GBN 64
#define GBK 16
__global__ __launch_bounds__(256) void gemm_nt_tanh(
    const float* __restrict__ A, const float* __restrict__ W,
    float* __restrict__ C, int M, int N, int K)
{
    __shared__ float As[GBK][GBM];
    __shared__ float Ws[GBK][GBN];
    const int tid = threadIdx.x;
    const int tx = tid & 15, ty = tid >> 4;
    const int row0 = blockIdx.y * GBM;
    const int col0 = blockIdx.x * GBN;

    float acc[4][4] = {};
    for (int k0 = 0; k0 < K; k0 += GBK) {
        #pragma unroll
        for (int i = tid; i < GBM * GBK; i += 256) {
            int r = i / GBK, kk = i % GBK;
            As[kk][r] = A[(row0 + r) * K + k0 + kk];
            Ws[kk][r] = W[(col0 + r) * K + k0 + kk];
        }
        __syncthreads();
        #pragma unroll
        for (int kk = 0; kk < GBK; kk++) {
            float4 a4 = *reinterpret_cast<const float4*>(&As[kk][ty * 4]);
            float4 b4 = *reinterpret_cast<const float4*>(&Ws[kk][tx * 4]);
            float a[4] = {a4.x, a4.y, a4.z, a4.w};
            float bv[4] = {b4.x, b4.y, b4.z, b4.w};
            #pragma unroll
            for (int i = 0; i < 4; i++)
                #pragma unroll
                for (int j = 0; j < 4; j++)
                    acc[i][j] = fmaf(a[i], bv[j], acc[i][j]);
        }
        __syncthreads();
    }
    #pragma unroll
    for (int i = 0; i < 4; i++)
        #pragma unroll
        for (int j = 0; j < 4; j++)
            C[(size_t)(row0 + ty * 4 + i) * N + col0 + tx * 4 + j] = tanhf(acc[i][j]);
}

// ---------------------------------------------------------------------------
// Recurrent kernel helpers
// ---------------------------------------------------------------------------
__device__ __forceinline__ float sigm(float x) { return 1.0f / (1.0f + expf(-x)); }

template <int CNT>
__device__ __forceinline__ float pdotf(const float4* __restrict__ W, int NOUT,
                                       const float* __restrict__ x, int r, int k0)
{
    const float4* x4 = reinterpret_cast<const float4*>(x);
    float4 a = {0.f,0.f,0.f,0.f};
    #pragma unroll
    for (int i = 0; i < CNT; i++) {
        int k = k0 + i;
        float4 w  = W[k * NOUT + r];
        float4 xv = x4[k];
        a.x = fmaf(w.x, xv.x, a.x); a.y = fmaf(w.y, xv.y, a.y);
        a.z = fmaf(w.z, xv.z, a.z); a.w = fmaf(w.w, xv.w, a.w);
    }
    return (a.x + a.y) + (a.z + a.w);
}

__device__ __forceinline__ float pdotr(const float4* __restrict__ W, int NOUT,
                                       const float* __restrict__ x, int r,
                                       int k0, int cnt)
{
    const float4* x4 = reinterpret_cast<const float4*>(x);
    float4 a = {0.f,0.f,0.f,0.f};
    #pragma unroll 4
    for (int k = k0; k < k0 + cnt; k++) {
        float4 w  = W[k * NOUT + r];
        float4 xv = x4[k];
        a.x = fmaf(w.x, xv.x, a.x); a.y = fmaf(w.y, xv.y, a.y);
        a.z = fmaf(w.z, xv.z, a.z); a.w = fmaf(w.w, xv.w, a.w);
    }
    return (a.x + a.y) + (a.z + a.w);
}

// Dynamic SMEM layout (~180 KB)
struct __align__(16) SM {
    // SMEM-cached small weights (packed layout preserved)
    float wfwg[4096];
    float wg[3][4096];
    float wout[8192];
    float wsg[16384];
    // per-chain state
    float prev[512];    // sample ring buffer
    float v[388];       // [feat2s(128) | prev_sub(64) | lookback(68) | sfw(128)]
    float sfw[128];
    float xg[128];      // GRU input [cur(64) | prev_sub(64)]
    float st[3][64];    // GRU states
    float sk[320];      // [o1 | o2 | o3 | fw | prev_sub]
    float sd[128];
    float so[128];
    float tmp[64];      // fw pre-GLU
    // partial buffers
    float pb_fw[512];       // Wfw slices; reused for SG (4x128) and OUT (8x64)
    float pb_gh[3][192];    // Whh @ st         (computed in prev step's tail)
    float pb_gip[3][192];   // Wih[:,64:128] @ prev_sub (mega)
    float pb_gic[2][192];   // Wih[:,0:64] @ cur (2 k-slices)
    float pb_sd[6][128];    // Wsd partials: [0]=prev [1]=fw [2]=o1 [3]=o2 [4,5]=o3
};

__global__ __launch_bounds__(512, 1) void recur_kernel(
    const float* __restrict__ prev_in,
    const float* __restrict__ Wp,
    float* __restrict__ outbuf)
{
    extern __shared__ unsigned char smem_raw[];
    SM& SL = *reinterpret_cast<SM*>(smem_raw);

    const int tid = threadIdx.x;
    const int b = blockIdx.x;

    const float4* Wfw4 = (const float4*)(Wp + OFF_FW);
    const float4* Wih4[3] = {(const float4*)(Wp + OFF_IH1),
                             (const float4*)(Wp + OFF_IH2),
                             (const float4*)(Wp + OFF_IH3)};
    const float4* Whh4[3] = {(const float4*)(Wp + OFF_HH1),
                             (const float4*)(Wp + OFF_HH2),
                             (const float4*)(Wp + OFF_HH3)};
    const float4* Wsd4 = (const float4*)(Wp + OFF_SD);

    // One-time: copy small weight matrices into SMEM
    {
        const float4* s1 = (const float4*)(Wp + OFF_FWG);
        float4* d1 = (float4*)SL.wfwg;
        for (int i = tid; i < 1024; i += 512) d1[i] = s1[i];
        #pragma unroll
        for (int m = 0; m < 3; m++) {
            const float4* s2 = (const float4*)(Wp + (m == 0 ? OFF_G1 : m == 1 ? OFF_G2 : OFF_G3));
            float4* d2 = (float4*)SL.wg[m];
            for (int i = tid; i < 1024; i += 512) d2[i] = s2[i];
        }
        const float4* s3 = (const float4*)(Wp + OFF_OUT);
        float4* d3 = (float4*)SL.wout;
        for (int i = tid; i < 2048; i += 512) d3[i] = s3[i];
        const float4* s4 = (const float4*)(Wp + OFF_SG);
        float4* d4 = (float4*)SL.wsg;
        for (int i = tid; i < 4096; i += 512) d4[i] = s4[i];
    }

    // init: previous samples + zero states; gh(step 0) = Whh @ 0 = 0.
    SL.prev[tid & 511] = prev_in[b * 512 + (tid & 511)];
    if (tid < 192) SL.st[tid >> 6][tid & 63] = 0.f;
    if (tid < 128) SL.sfw[tid] = 0.f;
    for (int i = tid; i < 576; i += 512) (&SL.pb_gh[0][0])[i] = 0.f;
    __syncthreads();

    const float4* WfwgS = (const float4*)SL.wfwg;
    const float4* WgS[3] = {(const float4*)SL.wg[0], (const float4*)SL.wg[1],
                            (const float4*)SL.wg[2]};
    const float4* WoutS = (const float4*)SL.wout;
    const float4* WsgS  = (const float4*)SL.wsg;

    for (int t = 0; t < FRN; t++) {
        const int p = g_P[b * FRN + t];
        for (int k = 0; k < 4; k++) {
            const int step = t * 4 + k;
            const int head = (step * 64) & 511;

            // --- Stage A: build v, xg[64:128], sk[256:320]
            if (tid < 388) {
                const int j = tid;
                float val;
                if (j < 128) {
                    val = g_C[(size_t)(b * FRN + t) * 512 + 4 * j + k];
                } else if (j < 192) {
                    int jj = j - 128;
                    val = SL.prev[(head + 448 + jj) & 511];   // prev_sub
                    SL.xg[64 + jj] = val;
                    SL.sk[256 + jj] = val;
                } else if (j < 260) {
                    int jj = j - 192;
                    int li = 510 - p + jj;
                    if (li >= 512) li -= p;
                    val = SL.prev[(head + li) & 511];          // lookback
                } else {
                    val = SL.sfw[j - 260];
                }
                SL.v[j] = val;
            }
            __syncthreads();

            // --- MEGA: Wfw slices + gip + sd_prev (gh comes from prev tail)
            {
                int s = tid >> 6, r = tid & 63;
                int cnt = 12 + (s == 0);
                int k0 = s * 12 + (s > 0);
                SL.pb_fw[s * 64 + r] = pdotr(Wfw4, 64, SL.v, r, k0, cnt);
            }
            #pragma unroll
            for (int pass = 0; pass < 2; pass++) {
                int id = tid + pass * 512;
                if (id < 576) {
                    int gr = (id >= 384) ? 2 : (id >= 192) ? 1 : 0;
                    int r = id - gr * 192;
                    SL.pb_gip[gr][r] = pdotf<16>(Wih4[gr], 192, SL.xg, r, 16);
                } else if (id < 704) {
                    int r = id - 576;
                    SL.pb_sd[0][r] = pdotf<16>(Wsd4, 128, SL.sk, r, 64);
                }
            }
            __syncthreads();

            // --- fw stage: warps 14-15 do fwred + fwGLU (named barrier);
            //     warps 0-11 prefetch GRU1 gi weights into registers.
            float4 wgi[8];
            if (tid >= 448) {
                int j = tid - 448;
                float sum = 0.f;
                #pragma unroll
                for (int i = 0; i < 8; i++) sum += SL.pb_fw[i * 64 + j];
                float tm = tanhf(sum);
                SL.tmp[j] = tm;
                asm volatile("bar.sync 1, 64;" ::: "memory");
                float g = pdotf<16>(WfwgS, 64, SL.tmp, j, 0);
                float f = tm * sigm(g);
                SL.sk[192 + j] = f;
                SL.xg[j] = f;
            } else if (tid < 384) {
                int s = tid / 192, r = tid % 192;
                #pragma unroll
                for (int i = 0; i < 8; i++)
                    wgi[i] = Wih4[0][(s * 8 + i) * 192 + r];
            }
            __syncthreads();

            // --- 3 GRU + GLU blocks
            #pragma unroll
            for (int gr = 0; gr < 3; gr++) {
                // gi (prefetched weights) + concurrent Wsd slice
                if (tid < 384) {
                    int s = tid / 192, r = tid % 192;
                    const float4* x4 = (const float4*)SL.xg;
                    float4 a = {0.f,0.f,0.f,0.f};
                    #pragma unroll
                    for (int i = 0; i < 8; i++) {
                        float4 w = wgi[i];
                        float4 xv = x4[s * 8 + i];
                        a.x = fmaf(w.x, xv.x, a.x); a.y = fmaf(w.y, xv.y, a.y);
                        a.z = fmaf(w.z, xv.z, a.z); a.w = fmaf(w.w, xv.w, a.w);
                    }
                    SL.pb_gic[s][r] = (a.x + a.y) + (a.z + a.w);
                } else {
                    int r = tid - 384;
                    int k0 = (gr == 0) ? 48 : (gr == 1) ? 0 : 16;
                    SL.pb_sd[1 + gr][r] = pdotf<16>(Wsd4, 128, SL.sk, r, k0);
                }
                __syncthreads();

                // elem + glu merged on warps 14-15; others prefetch next gi
                if (tid >= 448) {
                    int j = tid - 448;
                    float gir = SL.pb_gic[0][j]       + SL.pb_gic[1][j]       + SL.pb_gip[gr][j];
                    float giz = SL.pb_gic[0][64 + j]  + SL.pb_gic[1][64 + j]  + SL.pb_gip[gr][64 + j];
                    float gin = SL.pb_gic[0][128 + j] + SL.pb_gic[1][128 + j] + SL.pb_gip[gr][128 + j];
                    float r_ = sigm(gir + SL.pb_gh[gr][j]);
                    float z  = sigm(giz + SL.pb_gh[gr][64 + j]);
                    float n  = tanhf(gin + r_ * SL.pb_gh[gr][128 + j]);
                    float stn = (1.f - z) * n + z * SL.st[gr][j];
                    SL.st[gr][j] = stn;
                    asm volatile("bar.sync 1, 64;" ::: "memory");
                    float g = pdotf<16>(WgS[gr], 64, SL.st[gr], j, 0);
                    float o = stn * sigm(g);
                    SL.sk[gr * 64 + j] = o;
                    if (gr < 2) SL.xg[j] = o;
                } else if (tid < 384 && gr < 2) {
                    int s = tid / 192, r = tid % 192;
                    const float4* Wn = Wih4[gr + 1];
                    #pragma unroll
                    for (int i = 0; i < 8; i++)
                        wgi[i] = Wn[(s * 8 + i) * 192 + r];
                }
                __syncthreads();
            }

            // --- T1: sd o3 slices (256 thr) + gh part A for next step (256 thr)
            if (tid < 256) {
                int r = tid & 127, s = tid >> 7;
                SL.pb_sd[4 + s][r] = pdotf<8>(Wsd4, 128, SL.sk, r, 32 + s * 8);
            } else {
                int g = tid - 256;                 // 0..255
                int gr = (g >= 192) ? 1 : 0;
                int r = g - gr * 192;
                SL.pb_gh[gr][r] = pdotf<16>(Whh4[gr], 192, SL.st[gr], r, 0);
            }
            __syncthreads();

            // --- T2: sdred (128 thr) + gh part B (320 thr) + sfw copy (64 thr)
            if (tid < 128) {
                float sum = ((SL.pb_sd[2][tid] + SL.pb_sd[3][tid]) +
                             (SL.pb_sd[4][tid] + SL.pb_sd[5][tid])) +
                            (SL.pb_sd[1][tid] + SL.pb_sd[0][tid]);
                SL.sd[tid] = tanhf(sum);
            } else if (tid < 448) {
                int g = 256 + (tid - 128);         // 256..575
                int gr = (g >= 384) ? 2 : 1;
                int r = g - gr * 192;
                SL.pb_gh[gr][r] = pdotf<16>(Whh4[gr], 192, SL.st[gr], r, 0);
            } else {
                int j = tid - 448;
                SL.sfw[j] = SL.v[j];
                SL.sfw[j + 64] = SL.v[j + 64];
            }
            __syncthreads();

            // --- sg: gate partials (SMEM weights, 4 slices of 8)
            {
                int r = tid & 127, s = tid >> 7;
                SL.pb_fw[s * 128 + r] = pdotf<8>(WsgS, 128, SL.sd, r, s * 8);
            }
            __syncthreads();
            if (tid < 128) {
                float g = (SL.pb_fw[tid] + SL.pb_fw[128 + tid]) +
                          (SL.pb_fw[256 + tid] + SL.pb_fw[384 + tid]);
                SL.so[tid] = SL.sd[tid] * sigm(g);
            }
            __syncthreads();

            // --- out: (SMEM weights, 8 slices of 4)
            {
                int r = tid & 63, s = tid >> 6;
                SL.pb_fw[s * 64 + r] = pdotf<4>(WoutS, 64, SL.so, r, s * 4);
            }
            __syncthreads();
            if (tid < 64) {
                float sum = 0.f;
                #pragma unroll
                for (int i = 0; i < 8; i++) sum += SL.pb_fw[i * 64 + tid];
                float o = tanhf(sum);
                outbuf[(size_t)b * 25600 + (size_t)t * 256 + k * 64 + tid] = o;
                SL.prev[(head + tid) & 511] = o;
            }
            __syncthreads();
        }
    }
}

// ---------------------------------------------------------------------------
extern "C" void kernel_launch(void* const* d_in, const int* in_sizes, int n_in,
                              void* d_out, int out_size)
{
    const float* features = (const float*)d_in[0];
    const float* gfeat    = (const float*)d_in[1];
    const float* prev     = (const float*)d_in[2];
    const float* Wc1      = (const float*)d_in[3];
    const float* Wc2      = (const float*)d_in[4];
    const float* Wc3      = (const float*)d_in[5];
    float* out = (float*)d_out;

    float *pX, *pH1, *pH2, *pC, *pWp;
    cudaGetSymbolAddress((void**)&pX,  g_X);
    cudaGetSymbolAddress((void**)&pH1, g_H1);
    cudaGetSymbolAddress((void**)&pH2, g_H2);
    cudaGetSymbolAddress((void**)&pC,  g_C);
    cudaGetSymbolAddress((void**)&pWp, g_Wp);

    // Phase P: repack recurrent weights into coalesced layout
    struct PW { int idx, off, nout, K; };
    const PW pw[14] = {
        { 6, OFF_FW,  64, 388}, { 7, OFF_FWG, 64,  64},
        { 8, OFF_IH1, 192, 128}, { 9, OFF_HH1, 192, 64},
        {10, OFF_IH2, 192, 128}, {11, OFF_HH2, 192, 64},
        {12, OFF_IH3, 192, 128}, {13, OFF_HH3, 192, 64},
        {14, OFF_G1,  64,  64}, {15, OFF_G2,  64,  64}, {16, OFF_G3, 64, 64},
        {17, OFF_SG, 128, 128}, {18, OFF_SD, 128, 320}, {19, OFF_OUT, 64, 128},
    };
    for (int i = 0; i < 14; i++) {
        int n = pw[i].nout * pw[i].K;
        pack_w_kernel<<<(n + 255) / 256, 256>>>((const float*)d_in[pw[i].idx],
                                                pWp + pw[i].off,
                                                pw[i].nout, pw[i].K);
    }

    // Phase A: frame-feature conv stack (not recurrent)
    pack_kernel<<<6400, 256>>>(features, gfeat);
    gemm_nt_tanh<<<dim3(4, 100), 256>>>(pX,  Wc1, pH1, 6400, 256, 256);
    gemm_nt_tanh<<<dim3(4, 100), 256>>>(pH1, Wc2, pH2, 6400, 256, 256);
    gemm_nt_tanh<<<dim3(8, 100), 256>>>(pH2, Wc3, pC,  6400, 512, 256);

    // Phase B: persistent recurrent kernel (1 batch chain per CTA)
    static const int SMEM_BYTES = (int)sizeof(SM);
    cudaFuncSetAttribute(recur_kernel,
                         cudaFuncAttributeMaxDynamicSharedMemorySize, SMEM_BYTES);
    recur_kernel<<<64, 512, SMEM_BYTES>>>(prev, pWp, out);
}